// round 2
// baseline (speedup 1.0000x reference)
#include <cuda_runtime.h>
#include <math.h>

#define BB 128
#define TDIM 512
#define DIN 12
#define HH 64
#define DOUT 320
#define DHID 1280
#define BT (BB*TDIM)

// ---------------- static scratch (no allocs allowed) ----------------
__device__ float g_b64_a[BB*HH*TDIM];
__device__ float g_b64_b[BB*HH*TDIM];
__device__ float g_b64_c[BB*HH*TDIM];
__device__ float g_b320_a[BB*DOUT*TDIM];
__device__ float g_b320_b[BB*DOUT*TDIM];
__device__ float g_b320_c[BB*DOUT*TDIM];
__device__ float g_b1280[(size_t)BB*DHID*TDIM];
__device__ float g_interp[BT*DIN];
__device__ float g_wT_c01[HH*3*HH];
__device__ float g_wT_c02[HH*3*HH];
__device__ float g_wT_c1p[HH*1*DOUT];
__device__ float g_wT_c11[HH*3*DOUT];
__device__ float g_wT_c12[DOUT*3*DOUT];
__device__ float g_M12[144];
__device__ float g_c12[12];

// ---------------- helpers ----------------
__device__ __forceinline__ float gelu1(float x) {
    return 0.5f * x * (1.0f + erff(x * 0.7071067811865476f));
}
__device__ __forceinline__ unsigned long long splat2(float w) {
    unsigned long long r;
    asm("mov.b64 %0, {%1, %1};" : "=l"(r) : "f"(w));
    return r;
}
__device__ __forceinline__ void ffma2(unsigned long long& d, unsigned long long a,
                                      unsigned long long b) {
    asm("fma.rn.f32x2 %0, %1, %2, %3;" : "=l"(d) : "l"(a), "l"(b), "l"(d));
}
__device__ __forceinline__ float2 unpack2(unsigned long long v) {
    float2 r;
    asm("mov.b64 {%0, %1}, %2;" : "=f"(r.x), "=f"(r.y) : "l"(v));
    return r;
}

// w[co][ci][k] -> wT[ci*K+k][co]
__global__ void repack_w_kernel(const float* __restrict__ w, float* __restrict__ wT,
                                int COUT, int CIN, int KS) {
    int n = COUT * CIN * KS;
    for (int i = blockIdx.x * blockDim.x + threadIdx.x; i < n; i += gridDim.x * blockDim.x) {
        int k = i % KS;
        int ci = (i / KS) % CIN;
        int co = i / (KS * CIN);
        wT[(ci * KS + k) * COUT + co] = w[i];
    }
}

// M12 = fc_w @ fcr_w  (12x12), c12 = fc_b @ fcr_w + fcr_b
__global__ void m12_kernel(const float* __restrict__ fc_w, const float* __restrict__ fc_b,
                           const float* __restrict__ fcr_w, const float* __restrict__ fcr_b,
                           float* __restrict__ M12, float* __restrict__ c12) {
    int tid = threadIdx.x;
    if (tid < 144) {
        int i = tid / 12, j = tid % 12;
        float s = 0.f;
        for (int k = 0; k < DOUT; k++) s += fc_w[i * DOUT + k] * fcr_w[k * 12 + j];
        M12[tid] = s;
    } else if (tid < 156) {
        int j = tid - 144;
        float s = fcr_b[j];
        for (int k = 0; k < DOUT; k++) s += fc_b[k] * fcr_w[k * 12 + j];
        c12[j] = s;
    }
}

// input projection: x[B,T,12] @ w_in[12,64] + b_in -> out[B,64,T]
__global__ void proj_in_kernel(const float* __restrict__ x, const float* __restrict__ w,
                               const float* __restrict__ bi, float* __restrict__ out) {
    int b = blockIdx.y;
    int t = blockIdx.x * 128 + threadIdx.x;
    float xv[DIN];
#pragma unroll
    for (int i = 0; i < DIN; i++) xv[i] = x[(b * TDIM + t) * DIN + i];
    for (int c = 0; c < HH; c++) {
        float s = bi[c];
#pragma unroll
        for (int i = 0; i < DIN; i++) s += xv[i] * w[i * HH + c];
        out[(b * HH + c) * TDIM + t] = s;
    }
}

// ---------------- scalar conv (used for d=1 64-ch block0 convs) ----------------
template<int CIN, int COUT, int KS, int DIL, bool RES, bool GIN>
__global__ __launch_bounds__(256) void conv_kernel(
    const float* __restrict__ in, const float* __restrict__ wT,
    const float* __restrict__ bias, const float* __restrict__ res,
    float* __restrict__ out)
{
    constexpr int TTILE = 128, CT = 64, CK = 16;
    constexpr int HALO = (KS / 2) * DIL;
    constexpr int WROW = TTILE + 2 * HALO;

    __shared__ float sIn[CK][WROW];
    __shared__ float sW[CK * KS][CT];

    int b   = blockIdx.z;
    int t0  = blockIdx.x * TTILE;
    int co0 = blockIdx.y * CT;
    int tid = threadIdx.x;
    int tx = tid & 31, ty = tid >> 5;

    float acc[8][4];
#pragma unroll
    for (int a = 0; a < 8; a++)
#pragma unroll
        for (int c = 0; c < 4; c++) acc[a][c] = 0.f;

    for (int c0 = 0; c0 < CIN; c0 += CK) {
        for (int i = tid; i < CK * WROW; i += 256) {
            int idx = i % WROW, ci = i / WROW;
            int t = t0 + idx - HALO;
            float v = 0.f;
            if (t >= 0 && t < TDIM) v = in[(b * CIN + c0 + ci) * TDIM + t];
            if (GIN) v = gelu1(v);
            sIn[ci][idx] = v;
        }
        for (int i = tid; i < CK * KS * CT; i += 256) {
            int co = i % CT, rk = i / CT;
            sW[rk][co] = wT[(c0 * KS + rk) * COUT + co0 + co];
        }
        __syncthreads();

#pragma unroll 4
        for (int ci = 0; ci < CK; ci++) {
#pragma unroll
            for (int k = 0; k < KS; k++) {
                float iv[4], wv[8];
#pragma unroll
                for (int jt = 0; jt < 4; jt++) iv[jt] = sIn[ci][tx + 32 * jt + k * DIL];
#pragma unroll
                for (int jc = 0; jc < 8; jc++) wv[jc] = sW[ci * KS + k][ty + 8 * jc];
#pragma unroll
                for (int jc = 0; jc < 8; jc++)
#pragma unroll
                    for (int jt = 0; jt < 4; jt++) acc[jc][jt] += wv[jc] * iv[jt];
            }
        }
        __syncthreads();
    }

#pragma unroll
    for (int jc = 0; jc < 8; jc++) {
        int co = co0 + ty + 8 * jc;
        float bb = bias[co];
#pragma unroll
        for (int jt = 0; jt < 4; jt++) {
            int t = t0 + tx + 32 * jt;
            float v = acc[jc][jt] + bb;
            if (RES) v += res[(b * COUT + co) * TDIM + t];
            out[(b * COUT + co) * TDIM + t] = v;
        }
    }
}

// ---------------- f32x2 conv: requires even k*DIL shifts (DIL even or KS==1) ----
// thread tile: 8 co x 8 t (4 adjacent t-pairs). TTILE=256.
template<int CIN, int COUT, int KS, int DIL, bool RES, bool GIN, bool ROUT>
__global__ __launch_bounds__(256, 2) void conv_f2_kernel(
    const float* __restrict__ in, const float* __restrict__ wT,
    const float* __restrict__ bias, const float* __restrict__ res,
    float* __restrict__ out)
{
    constexpr int TTILE = 256, CT = 64, CK = 16;
    constexpr int HALO = (KS / 2) * DIL;
    constexpr int WROW = TTILE + 2 * HALO;

    __shared__ __align__(16) float sIn[CK][WROW];
    __shared__ float sW[CK * KS][CT];

    int b   = blockIdx.z;
    int t0  = blockIdx.x * TTILE;
    int co0 = blockIdx.y * CT;
    int tid = threadIdx.x;
    int tx = tid & 31, ty = tid >> 5;

    unsigned long long acc[8][4];
#pragma unroll
    for (int a = 0; a < 8; a++)
#pragma unroll
        for (int c = 0; c < 4; c++) acc[a][c] = 0ULL;

    for (int c0 = 0; c0 < CIN; c0 += CK) {
        for (int i = tid; i < CK * WROW; i += 256) {
            int idx = i % WROW, ci = i / WROW;
            int t = t0 + idx - HALO;
            float v = 0.f;
            if (t >= 0 && t < TDIM) v = in[(b * CIN + c0 + ci) * TDIM + t];
            if (GIN) v = gelu1(v);
            sIn[ci][idx] = v;
        }
        for (int i = tid; i < CK * KS * CT; i += 256) {
            int co = i % CT, rk = i / CT;
            sW[rk][co] = wT[(c0 * KS + rk) * COUT + co0 + co];
        }
        __syncthreads();

#pragma unroll 4
        for (int ci = 0; ci < CK; ci++) {
#pragma unroll
            for (int k = 0; k < KS; k++) {
                unsigned long long iv[4];
#pragma unroll
                for (int jp = 0; jp < 4; jp++)
                    iv[jp] = *(const unsigned long long*)&sIn[ci][2 * tx + 64 * jp + k * DIL];
#pragma unroll
                for (int jc = 0; jc < 8; jc++) {
                    unsigned long long ws = splat2(sW[ci * KS + k][ty + 8 * jc]);
#pragma unroll
                    for (int jp = 0; jp < 4; jp++) ffma2(acc[jc][jp], iv[jp], ws);
                }
            }
        }
        __syncthreads();
    }

#pragma unroll
    for (int jc = 0; jc < 8; jc++) {
        int co = co0 + ty + 8 * jc;
        float bb = bias[co];
#pragma unroll
        for (int jp = 0; jp < 4; jp++) {
            int t = t0 + 2 * tx + 64 * jp;
            float2 r = unpack2(acc[jc][jp]);
            r.x += bb; r.y += bb;
            if (RES) {
                float2 rv = *(const float2*)&res[(b * COUT + co) * TDIM + t];
                r.x += rv.x; r.y += rv.y;
            }
            if (ROUT) {
                r.x = r.x > 0.f ? r.x : 0.f;
                r.y = r.y > 0.f ? r.y : 0.f;
            }
            *(float2*)&out[(b * COUT + co) * TDIM + t] = r;
        }
    }
}

// ---------------- transpose [B,C,T] -> [B,T,C] ----------------
__global__ void transpose_kernel(const float* __restrict__ in, float* __restrict__ out, int C) {
    __shared__ float tile[32][33];
    int b = blockIdx.z;
    int t0 = blockIdx.x * 32, c0 = blockIdx.y * 32;
    int tx = threadIdx.x, ty = threadIdx.y;  // 32 x 8
#pragma unroll
    for (int i = 0; i < 32; i += 8)
        tile[ty + i][tx] = in[(b * C + c0 + ty + i) * TDIM + t0 + tx];
    __syncthreads();
#pragma unroll
    for (int i = 0; i < 32; i += 8)
        out[(b * TDIM + t0 + ty + i) * C + c0 + tx] = tile[tx][ty + i];
}

// ---------------- dense stage2: h[B,1280,T] (relu'd) @ W2[1280,12] + b2 -> [B*T,12]
__global__ __launch_bounds__(128) void dense2_kernel(
    const float* __restrict__ h, const float* __restrict__ W2,
    const float* __restrict__ b2, float* __restrict__ out)
{
    __shared__ float sW2[128][12];
    int b = blockIdx.y;
    int t = blockIdx.x * 128 + threadIdx.x;
    float acc[12];
#pragma unroll
    for (int o = 0; o < 12; o++) acc[o] = 0.f;

    for (int k0 = 0; k0 < DHID; k0 += 128) {
        __syncthreads();
        for (int i = threadIdx.x; i < 128 * 12; i += 128)
            sW2[i / 12][i % 12] = W2[(k0 + i / 12) * 12 + (i % 12)];
        __syncthreads();
#pragma unroll 4
        for (int kk = 0; kk < 128; kk++) {
            float v = h[((size_t)b * DHID + k0 + kk) * TDIM + t];
#pragma unroll
            for (int o = 0; o < 12; o++) acc[o] += v * sW2[kk][o];
        }
    }
#pragma unroll
    for (int o = 0; o < 12; o++) out[(b * TDIM + t) * 12 + o] = acc[o] + b2[o];
}

// outputs1 = outputs2 = interp @ M12 + c12
__global__ void outputs_kernel(const float* __restrict__ interp,
                               const float* __restrict__ M12, const float* __restrict__ c12,
                               float* __restrict__ o1, float* __restrict__ o2) {
    int r = blockIdx.x * blockDim.x + threadIdx.x;
    if (r >= BT) return;
    float xv[12];
#pragma unroll
    for (int i = 0; i < 12; i++) xv[i] = interp[r * 12 + i];
#pragma unroll
    for (int j = 0; j < 12; j++) {
        float s = c12[j];
#pragma unroll
        for (int i = 0; i < 12; i++) s += xv[i] * M12[i * 12 + j];
        o1[r * 12 + j] = s;
        o2[r * 12 + j] = s;
    }
}

// masks + passthrough copies
__global__ void tail_kernel(const float* __restrict__ x1, const float* __restrict__ x2,
                            float* __restrict__ om1, float* __restrict__ om2,
                            float* __restrict__ ox1, float* __restrict__ ox2) {
    int i = blockIdx.x * blockDim.x + threadIdx.x;
    if (i < BT * DIN) {
        float a = x1[i], b = x2[i];
        om1[i] = (a != 0.f) ? 1.f : 0.f;
        om2[i] = (b != 0.f) ? 1.f : 0.f;
        ox1[i] = a;
        ox2[i] = b;
    }
}

// ---------------- host side ----------------
struct ConvW { const float *c01b, *c02b, *c1pb, *c11b, *c12b; };

// result lands in b320c  [B,320,T]
static void run_encoder(const float* in, const float* w_in, const float* b_in,
                        const ConvW& cb,
                        float* wc01, float* wc02, float* wc1p, float* wc11, float* wc12,
                        float* b64a, float* b64b, float* b64c,
                        float* b320a, float* b320b, float* b320c) {
    dim3 g64(TDIM / 128, 1, BB);
    dim3 g320(TDIM / 256, DOUT / 64, BB);

    proj_in_kernel<<<dim3(TDIM / 128, BB), 128>>>(in, w_in, b_in, b64a);
    // block0 (d=1, gelu fused into input load)
    conv_kernel<HH, HH, 3, 1, false, true><<<g64, 256>>>(b64a, wc01, cb.c01b, nullptr, b64b);
    conv_kernel<HH, HH, 3, 1, true,  true><<<g64, 256>>>(b64b, wc02, cb.c02b, b64a, b64c);
    // block1 (f32x2): res = 1x1(h);  t = conv_d2(gelu(h));  out = conv_d2(gelu(t)) + res
    conv_f2_kernel<HH, DOUT, 1, 1, false, false, false><<<g320, 256>>>(b64c, wc1p, cb.c1pb, nullptr, b320a);
    conv_f2_kernel<HH, DOUT, 3, 2, false, true,  false><<<g320, 256>>>(b64c, wc11, cb.c11b, nullptr, b320b);
    conv_f2_kernel<DOUT, DOUT, 3, 2, true, true, false><<<g320, 256>>>(b320b, wc12, cb.c12b, b320a, b320c);
}

extern "C" void kernel_launch(void* const* d_in, const int* in_sizes, int n_in,
                              void* d_out, int out_size) {
    const float* x1 = (const float*)d_in[0];
    const float* x2 = (const float*)d_in[1];
    const float* X1 = (const float*)d_in[2];
    const float* X2 = (const float*)d_in[3];
    const float* w_in = (const float*)d_in[5];
    const float* b_in = (const float*)d_in[6];
    const float* c0_1_w = (const float*)d_in[7];
    const float* c0_1_b = (const float*)d_in[8];
    const float* c0_2_w = (const float*)d_in[9];
    const float* c0_2_b = (const float*)d_in[10];
    const float* c1_p_w = (const float*)d_in[11];
    const float* c1_p_b = (const float*)d_in[12];
    const float* c1_1_w = (const float*)d_in[13];
    const float* c1_1_b = (const float*)d_in[14];
    const float* c1_2_w = (const float*)d_in[15];
    const float* c1_2_b = (const float*)d_in[16];
    const float* ih_dense_w = (const float*)d_in[17];
    const float* ih_dense_b = (const float*)d_in[18];
    const float* ih_proj_w = (const float*)d_in[19];
    const float* ih_proj_b = (const float*)d_in[20];
    const float* fc_w = (const float*)d_in[21];
    const float* fc_b = (const float*)d_in[22];
    const float* fcr_w = (const float*)d_in[29];
    const float* fcr_b = (const float*)d_in[30];

    float *b64a, *b64b, *b64c, *b320a, *b320b, *b320c, *b1280, *interp;
    float *wc01, *wc02, *wc1p, *wc11, *wc12, *M12, *c12;
    cudaGetSymbolAddress((void**)&b64a, g_b64_a);
    cudaGetSymbolAddress((void**)&b64b, g_b64_b);
    cudaGetSymbolAddress((void**)&b64c, g_b64_c);
    cudaGetSymbolAddress((void**)&b320a, g_b320_a);
    cudaGetSymbolAddress((void**)&b320b, g_b320_b);
    cudaGetSymbolAddress((void**)&b320c, g_b320_c);
    cudaGetSymbolAddress((void**)&b1280, g_b1280);
    cudaGetSymbolAddress((void**)&interp, g_interp);
    cudaGetSymbolAddress((void**)&wc01, g_wT_c01);
    cudaGetSymbolAddress((void**)&wc02, g_wT_c02);
    cudaGetSymbolAddress((void**)&wc1p, g_wT_c1p);
    cudaGetSymbolAddress((void**)&wc11, g_wT_c11);
    cudaGetSymbolAddress((void**)&wc12, g_wT_c12);
    cudaGetSymbolAddress((void**)&M12, g_M12);
    cudaGetSymbolAddress((void**)&c12, g_c12);

    // weight repacks + fused 12x12 head matrix
    repack_w_kernel<<<48, 256>>>(c0_1_w, wc01, HH, HH, 3);
    repack_w_kernel<<<48, 256>>>(c0_2_w, wc02, HH, HH, 3);
    repack_w_kernel<<<80, 256>>>(c1_p_w, wc1p, DOUT, HH, 1);
    repack_w_kernel<<<240, 256>>>(c1_1_w, wc11, DOUT, HH, 3);
    repack_w_kernel<<<1200, 256>>>(c1_2_w, wc12, DOUT, DOUT, 3);
    m12_kernel<<<1, 256>>>(fc_w, fc_b, fcr_w, fcr_b, M12, c12);

    float* out = (float*)d_out;
    float* o_xw1 = out;
    float* o_xw2 = out + (size_t)BT * DOUT;
    float* o_o1  = out + 2 * (size_t)BT * DOUT;
    float* o_o2  = o_o1 + (size_t)BT * DIN;
    float* o_m1  = o_o2 + (size_t)BT * DIN;
    float* o_m2  = o_m1 + (size_t)BT * DIN;
    float* o_x1  = o_m2 + (size_t)BT * DIN;
    float* o_x2  = o_x1 + (size_t)BT * DIN;

    ConvW cb{c0_1_b, c0_2_b, c1_p_b, c1_1_b, c1_2_b};
    dim3 tgrid(TDIM / 32, DOUT / 32, BB), tblk(32, 8);

    // x_whole1 = enc(X1)
    run_encoder(X1, w_in, b_in, cb, wc01, wc02, wc1p, wc11, wc12,
                b64a, b64b, b64c, b320a, b320b, b320c);
    transpose_kernel<<<tgrid, tblk>>>(b320c, o_xw1, DOUT);

    // x_whole2 = enc(X2)
    run_encoder(X2, w_in, b_in, cb, wc01, wc02, wc1p, wc11, wc12,
                b64a, b64b, b64c, b320a, b320b, b320c);
    transpose_kernel<<<tgrid, tblk>>>(b320c, o_xw2, DOUT);

    // interp path on x1 (x2's interp path + GRU are provably dead: mask1 == 1)
    run_encoder(x1, w_in, b_in, cb, wc01, wc02, wc1p, wc11, wc12,
                b64a, b64b, b64c, b320a, b320b, b320c);
    // dense stage1 as 1x1 conv with relu, channel-major, no transpose needed.
    // ih_dense_w [320,1280] is already in wT layout ([ci][co], stride COUT).
    conv_f2_kernel<DOUT, DHID, 1, 1, false, false, true>
        <<<dim3(TDIM / 256, DHID / 64, BB), 256>>>(b320c, ih_dense_w, ih_dense_b, nullptr, b1280);
    dense2_kernel<<<dim3(TDIM / 128, BB), 128>>>(b1280, ih_proj_w, ih_proj_b, interp);
    outputs_kernel<<<(BT + 127) / 128, 128>>>(interp, M12, c12, o_o1, o_o2);
    tail_kernel<<<(BT * DIN + 255) / 256, 256>>>(x1, x2, o_m1, o_m2, o_x1, o_x2);
}

// round 3
// speedup vs baseline: 1.4482x; 1.4482x over previous
#include <cuda_runtime.h>
#include <math.h>

#define BB 128
#define NB 384          // 3 encoder inputs batched: [X1 | X2 | x1]
#define TDIM 512
#define DIN 12
#define HH 64
#define DOUT 320
#define BT (BB*TDIM)
#define SLICE_OFF ((size_t)BB*DOUT*TDIM)

// ---------------- static scratch (no allocs allowed) ----------------
__device__ float g_b64_a[(size_t)NB*HH*TDIM];
__device__ float g_b64_b[(size_t)NB*HH*TDIM];
__device__ float g_b64_c[(size_t)NB*HH*TDIM];
__device__ float g_b320_a[(size_t)NB*DOUT*TDIM];
__device__ float g_b320_b[(size_t)NB*DOUT*TDIM];
__device__ float g_b320_c[(size_t)NB*DOUT*TDIM];
__device__ float g_interp[BT*DIN];
__device__ float g_wT_c01[HH*3*HH];
__device__ float g_wT_c02[HH*3*HH];
__device__ float g_wT_c1p[HH*1*DOUT];
__device__ float g_wT_c11[HH*3*DOUT];
__device__ float g_wT_c12[DOUT*3*DOUT];
__device__ float g_M12[144];
__device__ float g_c12[12];

__device__ __forceinline__ float gelu1(float x) {
    return 0.5f * x * (1.0f + erff(x * 0.7071067811865476f));
}

// ---------------- setup: all weight repacks + fused 12x12 head matrix --------
__device__ __forceinline__ void repack_one(const float* __restrict__ w,
                                           float* __restrict__ wT,
                                           int COUT, int CIN, int KS, int i) {
    int k = i % KS;
    int ci = (i / KS) % CIN;
    int co = i / (KS * CIN);
    wT[(ci * KS + k) * COUT + co] = w[i];
}

__global__ void setup_kernel(
    const float* __restrict__ c01w, const float* __restrict__ c02w,
    const float* __restrict__ c1pw, const float* __restrict__ c11w,
    const float* __restrict__ c12w,
    const float* __restrict__ fc_w, const float* __restrict__ fc_b,
    const float* __restrict__ fcr_w, const float* __restrict__ fcr_b,
    float* __restrict__ wc01, float* __restrict__ wc02, float* __restrict__ wc1p,
    float* __restrict__ wc11, float* __restrict__ wc12,
    float* __restrict__ M12, float* __restrict__ c12)
{
    const int N0 = 12288, N1 = 12288, N2 = 20480, N3 = 61440, N4 = 307200;
    int idx = blockIdx.x * 256 + threadIdx.x;
    int stride = gridDim.x * 256;
    for (int i = idx; i < N0 + N1 + N2 + N3 + N4; i += stride) {
        int j = i;
        if (j < N0) { repack_one(c01w, wc01, HH, HH, 3, j); continue; }
        j -= N0;
        if (j < N1) { repack_one(c02w, wc02, HH, HH, 3, j); continue; }
        j -= N1;
        if (j < N2) { repack_one(c1pw, wc1p, DOUT, HH, 1, j); continue; }
        j -= N2;
        if (j < N3) { repack_one(c11w, wc11, DOUT, HH, 3, j); continue; }
        j -= N3;
        repack_one(c12w, wc12, DOUT, DOUT, 3, j);
    }
    if (blockIdx.x == 0) {
        int tid = threadIdx.x;
        if (tid < 144) {
            int i = tid / 12, j = tid % 12;
            float s = 0.f;
            for (int k = 0; k < DOUT; k++) s += fc_w[i * DOUT + k] * fcr_w[k * 12 + j];
            M12[tid] = s;
        } else if (tid < 156) {
            int j = tid - 144;
            float s = fcr_b[j];
            for (int k = 0; k < DOUT; k++) s += fc_b[k] * fcr_w[k * 12 + j];
            c12[j] = s;
        }
    }
}

// input projection for all 3 slices: x[B,T,12] @ w_in + b_in -> out[NB,64,T]
__global__ void proj_in3_kernel(const float* __restrict__ X1, const float* __restrict__ X2,
                                const float* __restrict__ x1,
                                const float* __restrict__ w, const float* __restrict__ bi,
                                float* __restrict__ out) {
    int bz = blockIdx.y;                 // 0..383
    int slice = bz >> 7, b = bz & 127;
    const float* x = (slice == 0) ? X1 : (slice == 1) ? X2 : x1;
    int t = blockIdx.x * 128 + threadIdx.x;
    float xv[DIN];
#pragma unroll
    for (int i = 0; i < DIN; i++) xv[i] = x[(b * TDIM + t) * DIN + i];
    for (int c = 0; c < HH; c++) {
        float s = bi[c];
#pragma unroll
        for (int i = 0; i < DIN; i++) s += xv[i] * w[i * HH + c];
        out[((size_t)bz * HH + c) * TDIM + t] = s;
    }
}

// ---------------- conv (k3 dilated / 1x1), channel-major, batch NB ----------
// in [NB,CIN,T], wT [CIN*KS][COUT], out [NB,COUT,T]; optional gelu-on-load / residual.
template<int CIN, int COUT, int KS, int DIL, bool RES, bool GIN>
__global__ __launch_bounds__(256) void conv_kernel(
    const float* __restrict__ in, const float* __restrict__ wT,
    const float* __restrict__ bias, const float* __restrict__ res,
    float* __restrict__ out)
{
    constexpr int TTILE = 128, CT = 64, CK = 16;
    constexpr int HALO = (KS / 2) * DIL;
    constexpr int WROW = TTILE + 2 * HALO;

    __shared__ float sIn[CK][WROW];
    __shared__ float sW[CK * KS][CT];

    size_t b = blockIdx.z;
    int t0  = blockIdx.x * TTILE;
    int co0 = blockIdx.y * CT;
    int tid = threadIdx.x;
    int tx = tid & 31, ty = tid >> 5;

    float acc[8][4];
#pragma unroll
    for (int a = 0; a < 8; a++)
#pragma unroll
        for (int c = 0; c < 4; c++) acc[a][c] = 0.f;

    for (int c0 = 0; c0 < CIN; c0 += CK) {
        for (int i = tid; i < CK * WROW; i += 256) {
            int idx = i % WROW, ci = i / WROW;
            int t = t0 + idx - HALO;
            float v = 0.f;
            if (t >= 0 && t < TDIM) v = in[(b * CIN + c0 + ci) * TDIM + t];
            if (GIN) v = gelu1(v);
            sIn[ci][idx] = v;
        }
        for (int i = tid; i < CK * KS * CT; i += 256) {
            int co = i % CT, rk = i / CT;
            sW[rk][co] = wT[(c0 * KS + rk) * COUT + co0 + co];
        }
        __syncthreads();

#pragma unroll 4
        for (int ci = 0; ci < CK; ci++) {
#pragma unroll
            for (int k = 0; k < KS; k++) {
                float iv[4], wv[8];
#pragma unroll
                for (int jt = 0; jt < 4; jt++) iv[jt] = sIn[ci][tx + 32 * jt + k * DIL];
#pragma unroll
                for (int jc = 0; jc < 8; jc++) wv[jc] = sW[ci * KS + k][ty + 8 * jc];
#pragma unroll
                for (int jc = 0; jc < 8; jc++)
#pragma unroll
                    for (int jt = 0; jt < 4; jt++) acc[jc][jt] += wv[jc] * iv[jt];
            }
        }
        __syncthreads();
    }

#pragma unroll
    for (int jc = 0; jc < 8; jc++) {
        int co = co0 + ty + 8 * jc;
        float bb = bias[co];
#pragma unroll
        for (int jt = 0; jt < 4; jt++) {
            int t = t0 + tx + 32 * jt;
            float v = acc[jc][jt] + bb;
            if (RES) v += res[(b * COUT + co) * TDIM + t];
            out[(b * COUT + co) * TDIM + t] = v;
        }
    }
}

// ---------------- transpose one slice [128,C,T] -> [128,T,C] ----------------
__global__ void transpose_kernel(const float* __restrict__ in, float* __restrict__ out, int C) {
    __shared__ float tile[32][33];
    size_t b = blockIdx.z;
    int t0 = blockIdx.x * 32, c0 = blockIdx.y * 32;
    int tx = threadIdx.x, ty = threadIdx.y;  // 32 x 8
#pragma unroll
    for (int i = 0; i < 32; i += 8)
        tile[ty + i][tx] = in[(b * C + c0 + ty + i) * TDIM + t0 + tx];
    __syncthreads();
#pragma unroll
    for (int i = 0; i < 32; i += 8)
        out[(b * TDIM + t0 + ty + i) * C + c0 + tx] = tile[tx][ty + i];
}

// ------- fused dense head (channel-major input): relu(X@W1+b1)@W2+b2 -> [M,12]
// X is [128,320,T] channel-major (slice view); logical row r = b*T + t.
__global__ __launch_bounds__(256) void dense_interp_kernel(
    const float* __restrict__ X,    // [128,320,512] channel-major
    const float* __restrict__ W1,   // [320,1280]
    const float* __restrict__ b1,   // [1280]
    const float* __restrict__ W2,   // [1280,12]
    const float* __restrict__ b2,   // [12]
    float* __restrict__ out)        // [M,12]
{
    __shared__ float sX[16][65];
    __shared__ float sW1[16][128];
    __shared__ float sH[64][129];

    int row0 = blockIdx.x * 64;
    size_t bslice = row0 >> 9;      // row0 / 512
    int t0 = row0 & 511;
    int tid = threadIdx.x;
    int tx = tid & 31, ty = tid >> 5;

    float yacc[3] = {0.f, 0.f, 0.f};

    for (int ch = 0; ch < 10; ch++) {
        float acc[8][4];
#pragma unroll
        for (int a = 0; a < 8; a++)
#pragma unroll
            for (int c = 0; c < 4; c++) acc[a][c] = 0.f;

        for (int kt = 0; kt < 20; kt++) {
            // channel-major load: coalesced along t
            for (int i = tid; i < 16 * 64; i += 256) {
                int r = i & 63, kk = i >> 6;
                sX[kk][r] = X[(bslice * DOUT + kt * 16 + kk) * TDIM + t0 + r];
            }
            for (int i = tid; i < 16 * 128; i += 256) {
                int c = i & 127, kk = i >> 7;
                sW1[kk][c] = W1[(kt * 16 + kk) * 1280 + ch * 128 + c];
            }
            __syncthreads();
#pragma unroll 4
            for (int kk = 0; kk < 16; kk++) {
                float xv[8], wv[4];
#pragma unroll
                for (int jr = 0; jr < 8; jr++) xv[jr] = sX[kk][ty + 8 * jr];
#pragma unroll
                for (int jc = 0; jc < 4; jc++) wv[jc] = sW1[kk][tx + 32 * jc];
#pragma unroll
                for (int jr = 0; jr < 8; jr++)
#pragma unroll
                    for (int jc = 0; jc < 4; jc++) acc[jr][jc] += xv[jr] * wv[jc];
            }
            __syncthreads();
        }
#pragma unroll
        for (int jc = 0; jc < 4; jc++) {
            float bb = b1[ch * 128 + tx + 32 * jc];
#pragma unroll
            for (int jr = 0; jr < 8; jr++) {
                float v = acc[jr][jc] + bb;
                sH[ty + 8 * jr][tx + 32 * jc] = v > 0.f ? v : 0.f;
            }
        }
        __syncthreads();
#pragma unroll
        for (int q = 0; q < 3; q++) {
            int p = tid + 256 * q;
            int r = p / 12, o = p % 12;
            float s = 0.f;
#pragma unroll 8
            for (int k = 0; k < 128; k++) s += sH[r][k] * W2[(ch * 128 + k) * 12 + o];
            yacc[q] += s;
        }
        __syncthreads();
    }
#pragma unroll
    for (int q = 0; q < 3; q++) {
        int p = tid + 256 * q;
        int r = p / 12, o = p % 12;
        out[(row0 + r) * 12 + o] = yacc[q] + b2[o];
    }
}

// ---- finale: outputs1/2 = interp @ M12 + c12, masks + passthrough copies ----
__global__ void finale_kernel(const float* __restrict__ interp,
                              const float* __restrict__ M12, const float* __restrict__ c12,
                              const float* __restrict__ x1, const float* __restrict__ x2,
                              float* __restrict__ o1, float* __restrict__ o2,
                              float* __restrict__ om1, float* __restrict__ om2,
                              float* __restrict__ ox1, float* __restrict__ ox2) {
    int r = blockIdx.x * blockDim.x + threadIdx.x;
    if (r >= BT) return;
    float xv[12];
#pragma unroll
    for (int i = 0; i < 12; i++) xv[i] = interp[r * 12 + i];
#pragma unroll
    for (int j = 0; j < 12; j++) {
        float s = c12[j];
#pragma unroll
        for (int i = 0; i < 12; i++) s += xv[i] * M12[i * 12 + j];
        o1[r * 12 + j] = s;
        o2[r * 12 + j] = s;
    }
#pragma unroll
    for (int j = 0; j < 12; j++) {
        float a = x1[r * 12 + j], b = x2[r * 12 + j];
        om1[r * 12 + j] = (a != 0.f) ? 1.f : 0.f;
        om2[r * 12 + j] = (b != 0.f) ? 1.f : 0.f;
        ox1[r * 12 + j] = a;
        ox2[r * 12 + j] = b;
    }
}

// ---------------- host side ----------------
extern "C" void kernel_launch(void* const* d_in, const int* in_sizes, int n_in,
                              void* d_out, int out_size) {
    const float* x1 = (const float*)d_in[0];
    const float* x2 = (const float*)d_in[1];
    const float* X1 = (const float*)d_in[2];
    const float* X2 = (const float*)d_in[3];
    const float* w_in = (const float*)d_in[5];
    const float* b_in = (const float*)d_in[6];
    const float* c0_1_w = (const float*)d_in[7];
    const float* c0_1_b = (const float*)d_in[8];
    const float* c0_2_w = (const float*)d_in[9];
    const float* c0_2_b = (const float*)d_in[10];
    const float* c1_p_w = (const float*)d_in[11];
    const float* c1_p_b = (const float*)d_in[12];
    const float* c1_1_w = (const float*)d_in[13];
    const float* c1_1_b = (const float*)d_in[14];
    const float* c1_2_w = (const float*)d_in[15];
    const float* c1_2_b = (const float*)d_in[16];
    const float* ih_dense_w = (const float*)d_in[17];
    const float* ih_dense_b = (const float*)d_in[18];
    const float* ih_proj_w = (const float*)d_in[19];
    const float* ih_proj_b = (const float*)d_in[20];
    const float* fc_w = (const float*)d_in[21];
    const float* fc_b = (const float*)d_in[22];
    const float* fcr_w = (const float*)d_in[29];
    const float* fcr_b = (const float*)d_in[30];

    float *b64a, *b64b, *b64c, *b320a, *b320b, *b320c, *interp;
    float *wc01, *wc02, *wc1p, *wc11, *wc12, *M12, *c12;
    cudaGetSymbolAddress((void**)&b64a, g_b64_a);
    cudaGetSymbolAddress((void**)&b64b, g_b64_b);
    cudaGetSymbolAddress((void**)&b64c, g_b64_c);
    cudaGetSymbolAddress((void**)&b320a, g_b320_a);
    cudaGetSymbolAddress((void**)&b320b, g_b320_b);
    cudaGetSymbolAddress((void**)&b320c, g_b320_c);
    cudaGetSymbolAddress((void**)&interp, g_interp);
    cudaGetSymbolAddress((void**)&wc01, g_wT_c01);
    cudaGetSymbolAddress((void**)&wc02, g_wT_c02);
    cudaGetSymbolAddress((void**)&wc1p, g_wT_c1p);
    cudaGetSymbolAddress((void**)&wc11, g_wT_c11);
    cudaGetSymbolAddress((void**)&wc12, g_wT_c12);
    cudaGetSymbolAddress((void**)&M12, g_M12);
    cudaGetSymbolAddress((void**)&c12, g_c12);

    float* out = (float*)d_out;
    float* o_xw1 = out;
    float* o_xw2 = out + (size_t)BT * DOUT;
    float* o_o1  = out + 2 * (size_t)BT * DOUT;
    float* o_o2  = o_o1 + (size_t)BT * DIN;
    float* o_m1  = o_o2 + (size_t)BT * DIN;
    float* o_m2  = o_m1 + (size_t)BT * DIN;
    float* o_x1  = o_m2 + (size_t)BT * DIN;
    float* o_x2  = o_x1 + (size_t)BT * DIN;

    // launch 0: setup (repacks + M12)
    setup_kernel<<<1616, 256>>>(c0_1_w, c0_2_w, c1_p_w, c1_1_w, c1_2_w,
                                fc_w, fc_b, fcr_w, fcr_b,
                                wc01, wc02, wc1p, wc11, wc12, M12, c12);
    // launch 1: input projection for all 3 slices
    proj_in3_kernel<<<dim3(TDIM / 128, NB), 128>>>(X1, X2, x1, w_in, b_in, b64a);

    dim3 g64(TDIM / 128, 1, NB);
    dim3 g320(TDIM / 128, DOUT / 64, NB);
    // launches 2-6: batched encoder (slices [X1|X2|x1])
    conv_kernel<HH, HH, 3, 1, false, true><<<g64, 256>>>(b64a, wc01, c0_1_b, nullptr, b64b);
    conv_kernel<HH, HH, 3, 1, true,  true><<<g64, 256>>>(b64b, wc02, c0_2_b, b64a, b64c);
    conv_kernel<HH, DOUT, 1, 1, false, false><<<g320, 256>>>(b64c, wc1p, c1_p_b, nullptr, b320a);
    conv_kernel<HH, DOUT, 3, 2, false, true><<<g320, 256>>>(b64c, wc11, c1_1_b, nullptr, b320b);
    conv_kernel<DOUT, DOUT, 3, 2, true, true><<<g320, 256>>>(b320b, wc12, c1_2_b, b320a, b320c);

    // launches 7-8: x_whole1 / x_whole2 transposes (slices 0,1)
    dim3 tgrid(TDIM / 32, DOUT / 32, BB), tblk(32, 8);
    transpose_kernel<<<tgrid, tblk>>>(b320c, o_xw1, DOUT);
    transpose_kernel<<<tgrid, tblk>>>(b320c + SLICE_OFF, o_xw2, DOUT);

    // launch 9: dense interp head on slice 2 (channel-major, no transpose)
    dense_interp_kernel<<<BT / 64, 256>>>(b320c + 2 * SLICE_OFF,
                                          ih_dense_w, ih_dense_b,
                                          ih_proj_w, ih_proj_b, interp);
    // launch 10: outputs + masks + passthrough (GRU provably dead: mask1 == 1)
    finale_kernel<<<(BT + 127) / 128, 128>>>(interp, M12, c12, x1, x2,
                                             o_o1, o_o2, o_m1, o_m2, o_x1, o_x2);
}